// round 16
// baseline (speedup 1.0000x reference)
// Round 15.
//
// Post-mortem R14: cvt hoist worked as theorized (alu 28.7->9.2, sums
// 74.6->65.4, total 307.8 = new best). But sums is still only 42.9% tensor
// and the attn chain (sums 65 + write ~110 by subtraction) = ~175us of 308,
// and it computes every score TWICE (4.3 GMAC in each pass) plus pays a
// separate rsuminv round-trip and double K streaming.
//
// This round: single fused attention kernel. Block = (32 q rows, b), 512
// threads, 16 warps (wq 2 x wk 8). For each head: stream K in 128-key
// cp.async double-buffered chunks; warp (wq,wk) computes its 16q x 16k slice
// per chunk into persistent registers acc[16][4] (full 16q x 128k per warp
// after 8 chunks = the entire score row block resident in registers).
// Then: exp in place (computed ONCE), quad-shfl + cross-warp smem reduce for
// row sums, scale by 1/sum, write normalized attn directly, and accumulate
// P_avg into an smem tile (each location owned by one thread, no atomics).
// After all 8 heads, dump P_avg smem -> gmem. Scores computed once (4.3
// GMAC not 8.6), no rsuminv traffic, K read once per head, exp once.
// smem = 2xQ stage + 2xK stage + pav tile = 219KB -> 1 CTA/SM, 16 warps.
//
// Prediction: attn chain 175 -> ~100-110us (MMA ~35us at sums-kernel rates,
// LDS ~57us from the smaller 16x16 warp tile being the new binding pipe,
// store 256MB overlapped); total 307.8 -> ~235-250us; rel_err ~5e-4
// unchanged. If fused lands >130us, the 4-LDS/MMA fragment ratio is the
// wall and next round switches score fragments to ldmatrix-free wider
// tiles or tcgen05.

#include <cuda_runtime.h>
#include <cuda_bf16.h>
#include <math.h>
#include <stdint.h>

#define NB 8
#define SS 1024
#define DD 512
#define NH 8
#define DK 64
#define MROWS (NB * SS)
#define OUT_ELEMS (NB * SS * DD)

__device__ float g_qh[MROWS * DD];
__device__ float g_kh[MROWS * DD];
__device__ float g_vs[MROWS * DK];
__device__ float g_pavg[NB * SS * SS];
__device__ float g_head[MROWS * DK];

__device__ __forceinline__ uint32_t f2tf32(float x) {
    uint32_t r;
    asm("cvt.rna.tf32.f32 %0, %1;" : "=r"(r) : "f"(x));
    return r;
}

__device__ __forceinline__ void mma_tf32(float* d, const uint32_t* a,
                                         const uint32_t* b, const float* c) {
    asm volatile(
        "mma.sync.aligned.m16n8k8.row.col.f32.tf32.tf32.f32 "
        "{%0,%1,%2,%3}, {%4,%5,%6,%7}, {%8,%9}, {%10,%11,%12,%13};"
        : "=f"(d[0]), "=f"(d[1]), "=f"(d[2]), "=f"(d[3])
        : "r"(a[0]), "r"(a[1]), "r"(a[2]), "r"(a[3]),
          "r"(b[0]), "r"(b[1]),
          "f"(c[0]), "f"(c[1]), "f"(c[2]), "f"(c[3]));
}

__device__ __forceinline__ void cp_async16(uint32_t dst, const void* src) {
    asm volatile("cp.async.cg.shared.global [%0], [%1], 16;" :: "r"(dst), "l"(src));
}
__device__ __forceinline__ void cp_commit() {
    asm volatile("cp.async.commit_group;");
}
__device__ __forceinline__ void cp_wait1() {
    asm volatile("cp.async.wait_group 1;");
}

__device__ __forceinline__ float maybe_tf32(float x, int cvt) {
    return cvt ? __uint_as_float(f2tf32(x)) : x;
}

// ---------------------------------------------------------------------------
// Pipelined MMA GEMM-NT: C[M,N] = A[M,K] * W[N,K]^T, tf32.
// ---------------------------------------------------------------------------
#define GST 36
#define PROJ_STAGE (192 * GST)
#define PROJ_SMEM (2 * PROJ_STAGE * 4)

__global__ __launch_bounds__(256, 2)
void gemm_nt_mma2(const float* __restrict__ A, const float* __restrict__ W,
                  float* __restrict__ C, int M, int N, int K, int cvt_out) {
    extern __shared__ float sm[];
    const int m0 = blockIdx.y * 128;
    const int n0 = blockIdx.x * 64;
    const int tid = threadIdx.x;
    const int wid = tid >> 5, lane = tid & 31;
    const int lr = lane >> 2, lc = lane & 3;
    const int wm = (wid >> 1) * 32;
    const int wn = (wid & 1) * 32;

    const uint32_t smem_base = (uint32_t)__cvta_generic_to_shared(sm);

    float acc[2][4][4] = {};
    const int kt = K / 32;

    {
        uint32_t As_u = smem_base;
        uint32_t Ws_u = smem_base + 128 * GST * 4;
#pragma unroll
        for (int t = 0; t < 4; t++) {
            int s = tid + t * 256;
            int r = s >> 3, c = (s & 7) * 4;
            cp_async16(As_u + (r * GST + c) * 4, A + (size_t)(m0 + r) * K + c);
        }
#pragma unroll
        for (int t = 0; t < 2; t++) {
            int s = tid + t * 256;
            int r = s >> 3, c = (s & 7) * 4;
            cp_async16(Ws_u + (r * GST + c) * 4, W + (size_t)(n0 + r) * K + c);
        }
    }
    cp_commit();

    for (int it = 0; it < kt; it++) {
        if (it + 1 < kt) {
            int k0 = (it + 1) * 32;
            uint32_t st = smem_base + ((it + 1) & 1) * PROJ_STAGE * 4;
            uint32_t As_u = st;
            uint32_t Ws_u = st + 128 * GST * 4;
#pragma unroll
            for (int t = 0; t < 4; t++) {
                int s = tid + t * 256;
                int r = s >> 3, c = (s & 7) * 4;
                cp_async16(As_u + (r * GST + c) * 4, A + (size_t)(m0 + r) * K + k0 + c);
            }
#pragma unroll
            for (int t = 0; t < 2; t++) {
                int s = tid + t * 256;
                int r = s >> 3, c = (s & 7) * 4;
                cp_async16(Ws_u + (r * GST + c) * 4, W + (size_t)(n0 + r) * K + k0 + c);
            }
        }
        cp_commit();
        cp_wait1();
        __syncthreads();

        const float* As = sm + (it & 1) * PROJ_STAGE;
        const float* Ws = As + 128 * GST;
#pragma unroll
        for (int kk = 0; kk < 32; kk += 8) {
            uint32_t a[2][4], b[4][2];
#pragma unroll
            for (int mi = 0; mi < 2; mi++) {
                int r0 = wm + mi * 16 + lr;
                a[mi][0] = f2tf32(As[r0 * GST + kk + lc]);
                a[mi][1] = f2tf32(As[(r0 + 8) * GST + kk + lc]);
                a[mi][2] = f2tf32(As[r0 * GST + kk + lc + 4]);
                a[mi][3] = f2tf32(As[(r0 + 8) * GST + kk + lc + 4]);
            }
#pragma unroll
            for (int nj = 0; nj < 4; nj++) {
                int rn = wn + nj * 8 + lr;
                b[nj][0] = f2tf32(Ws[rn * GST + kk + lc]);
                b[nj][1] = f2tf32(Ws[rn * GST + kk + lc + 4]);
            }
#pragma unroll
            for (int mi = 0; mi < 2; mi++)
#pragma unroll
                for (int nj = 0; nj < 4; nj++)
                    mma_tf32(acc[mi][nj], a[mi], b[nj], acc[mi][nj]);
        }
        __syncthreads();
    }

#pragma unroll
    for (int mi = 0; mi < 2; mi++) {
        int row = m0 + wm + mi * 16 + lr;
#pragma unroll
        for (int nj = 0; nj < 4; nj++) {
            int col = n0 + wn + nj * 8 + 2 * lc;
            *(float2*)(C + (size_t)row * N + col) =
                make_float2(maybe_tf32(acc[mi][nj][0], cvt_out),
                            maybe_tf32(acc[mi][nj][1], cvt_out));
            *(float2*)(C + (size_t)(row + 8) * N + col) =
                make_float2(maybe_tf32(acc[mi][nj][2], cvt_out),
                            maybe_tf32(acc[mi][nj][3], cvt_out));
        }
    }
}

// ---------------------------------------------------------------------------
// Pipelined batched MMA GEMM-NN: C_b[M,N] = A_b[M,K] * B_b[K,N], tf32.
// ---------------------------------------------------------------------------
#define NNST_A 36
#define NNST_B 72
#define NN_STAGE (64 * NNST_A + 32 * NNST_B)

__global__ __launch_bounds__(256, 2)
void gemm_nn_mma(const float* __restrict__ A, const float* __restrict__ B,
                 float* __restrict__ C, int M, int N, int K,
                 size_t strideA, size_t strideB, size_t strideC) {
    __shared__ float sm[2 * NN_STAGE];
    const float* Ab = A + (size_t)blockIdx.z * strideA;
    const float* Bb = B + (size_t)blockIdx.z * strideB;
    float* Cb = C + (size_t)blockIdx.z * strideC;
    const int m0 = blockIdx.y * 64;
    const int n0 = blockIdx.x * 64;
    const int tid = threadIdx.x;
    const int wid = tid >> 5, lane = tid & 31;
    const int lr = lane >> 2, lc = lane & 3;
    const int wm = (wid >> 1) * 16;
    const int wn = (wid & 1) * 32;

    const uint32_t smem_base = (uint32_t)__cvta_generic_to_shared(sm);
    float acc[4][4] = {};
    const int kt = K / 32;

    {
        uint32_t As_u = smem_base;
        uint32_t Bs_u = smem_base + 64 * NNST_A * 4;
#pragma unroll
        for (int t = 0; t < 2; t++) {
            int s = tid + t * 256;
            int r = s >> 3, c = (s & 7) * 4;
            cp_async16(As_u + (r * NNST_A + c) * 4, Ab + (size_t)(m0 + r) * K + c);
        }
#pragma unroll
        for (int t = 0; t < 2; t++) {
            int s = tid + t * 256;
            int r = s >> 4, c = (s & 15) * 4;
            cp_async16(Bs_u + (r * NNST_B + c) * 4, Bb + (size_t)r * N + n0 + c);
        }
    }
    cp_commit();

    for (int it = 0; it < kt; it++) {
        if (it + 1 < kt) {
            int k0 = (it + 1) * 32;
            uint32_t st = smem_base + ((it + 1) & 1) * NN_STAGE * 4;
            uint32_t As_u = st;
            uint32_t Bs_u = st + 64 * NNST_A * 4;
#pragma unroll
            for (int t = 0; t < 2; t++) {
                int s = tid + t * 256;
                int r = s >> 3, c = (s & 7) * 4;
                cp_async16(As_u + (r * NNST_A + c) * 4, Ab + (size_t)(m0 + r) * K + k0 + c);
            }
#pragma unroll
            for (int t = 0; t < 2; t++) {
                int s = tid + t * 256;
                int r = s >> 4, c = (s & 15) * 4;
                cp_async16(Bs_u + (r * NNST_B + c) * 4, Bb + (size_t)(k0 + r) * N + n0 + c);
            }
        }
        cp_commit();
        cp_wait1();
        __syncthreads();

        const float* As = sm + (it & 1) * NN_STAGE;
        const float* Bs = As + 64 * NNST_A;
#pragma unroll
        for (int kk = 0; kk < 32; kk += 8) {
            uint32_t a[4], b[4][2];
            int r0 = wm + lr;
            a[0] = f2tf32(As[r0 * NNST_A + kk + lc]);
            a[1] = f2tf32(As[(r0 + 8) * NNST_A + kk + lc]);
            a[2] = f2tf32(As[r0 * NNST_A + kk + lc + 4]);
            a[3] = f2tf32(As[(r0 + 8) * NNST_A + kk + lc + 4]);
#pragma unroll
            for (int nj = 0; nj < 4; nj++) {
                int rn = wn + nj * 8 + lr;
                b[nj][0] = __float_as_uint(Bs[(kk + lc) * NNST_B + rn]);
                b[nj][1] = __float_as_uint(Bs[(kk + lc + 4) * NNST_B + rn]);
            }
#pragma unroll
            for (int nj = 0; nj < 4; nj++)
                mma_tf32(acc[nj], a, b[nj], acc[nj]);
        }
        __syncthreads();
    }

    {
        int row = m0 + wm + lr;
#pragma unroll
        for (int nj = 0; nj < 4; nj++) {
            int col = n0 + wn + nj * 8 + 2 * lc;
            *(float2*)(Cb + (size_t)row * N + col) =
                make_float2(acc[nj][0], acc[nj][1]);
            *(float2*)(Cb + (size_t)(row + 8) * N + col) =
                make_float2(acc[nj][2], acc[nj][3]);
        }
    }
}

// ---------------------------------------------------------------------------
// Fused attention: scores (once) + softmax + attn write + P_avg accumulate.
// Block = (32 q rows, b), 512 threads, 16 warps (wq 2 x wk 8).
// qh/kh are pre-rounded tf32 (no cvt in hot loop).
// ---------------------------------------------------------------------------
#define QST 68
#define PST 1032
#define FQ_STAGE (32 * QST)
#define FK_STAGE (128 * QST)
#define FUSED_SMEM ((2 * FQ_STAGE + 2 * FK_STAGE + 32 * PST) * 4)

__global__ __launch_bounds__(512, 1)
void attn_fused_kernel(const float* __restrict__ qh,
                       const float* __restrict__ kh,
                       float* __restrict__ attn_out,
                       float* __restrict__ pavg) {
    extern __shared__ float smf[];
    float* qbuf = smf;                               // 2 stages of [32][QST]
    float* kbuf = smf + 2 * FQ_STAGE;                // 2 stages of [128][QST]
    float* pav  = smf + 2 * FQ_STAGE + 2 * FK_STAGE; // [32][PST]
    __shared__ float ssum[8][32];

    const int q0 = blockIdx.x * 32;
    const int b  = blockIdx.y;
    const int tid = threadIdx.x;
    const int wid = tid >> 5, lane = tid & 31;
    const int lr = lane >> 2, lc = lane & 3;
    const int wq = wid >> 3, wk = wid & 7;
    const int rl0 = wq * 16 + lr;                    // local q row (and +8)

    const uint32_t q_u = (uint32_t)__cvta_generic_to_shared(qbuf);
    const uint32_t k_u = (uint32_t)__cvta_generic_to_shared(kbuf);

    const float* qg = qh + (size_t)(b * SS + q0) * DD;  // + h*DK
    const float* kg = kh + (size_t)(b * SS) * DD;       // + h*DK

    // zero pav
    for (int i = tid; i < 32 * PST; i += 512) pav[i] = 0.f;

    // prologue: Q head0 (512 float4 -> 1/thread), K head0 chunk0 (4/thread)
    {
        int r = tid >> 4, c4 = (tid & 15) * 4;
        cp_async16(q_u + (r * QST + c4) * 4, qg + (size_t)r * DD + c4);
#pragma unroll
        for (int t = 0; t < 4; t++) {
            int s = tid + t * 512;
            int rr = s >> 4, cc = (s & 15) * 4;
            cp_async16(k_u + (rr * QST + cc) * 4, kg + (size_t)rr * DD + cc);
        }
    }
    cp_commit();
    __syncthreads();  // pav zeros visible

    int it = 0;
    for (int h = 0; h < NH; h++) {
        float acc[16][4];
#pragma unroll
        for (int tj = 0; tj < 16; tj++)
#pragma unroll
            for (int i = 0; i < 4; i++) acc[tj][i] = 0.f;

        for (int ck = 0; ck < 8; ck++, it++) {
            if (!(h == 7 && ck == 7)) {
                int nh  = (ck == 7) ? h + 1 : h;
                int nck = (ck == 7) ? 0 : ck + 1;
                uint32_t kd = k_u + ((it + 1) & 1) * FK_STAGE * 4;
                const float* ksrc = kg + nh * DK + (size_t)nck * 128 * DD;
#pragma unroll
                for (int t = 0; t < 4; t++) {
                    int s = tid + t * 512;
                    int rr = s >> 4, cc = (s & 15) * 4;
                    cp_async16(kd + (rr * QST + cc) * 4, ksrc + (size_t)rr * DD + cc);
                }
                if (ck == 6 && h < 7) {
                    uint32_t qd = q_u + ((h + 1) & 1) * FQ_STAGE * 4;
                    const float* qsrc = qg + (h + 1) * DK;
                    int r = tid >> 4, c4 = (tid & 15) * 4;
                    cp_async16(qd + (r * QST + c4) * 4, qsrc + (size_t)r * DD + c4);
                }
            }
            cp_commit();
            cp_wait1();
            __syncthreads();

            const float* qs = qbuf + (h & 1) * FQ_STAGE;
            const float* ks = kbuf + (it & 1) * FK_STAGE;

#pragma unroll
            for (int kk = 0; kk < DK; kk += 8) {
                uint32_t a[4];
                a[0] = __float_as_uint(qs[rl0 * QST + kk + lc]);
                a[1] = __float_as_uint(qs[(rl0 + 8) * QST + kk + lc]);
                a[2] = __float_as_uint(qs[rl0 * QST + kk + lc + 4]);
                a[3] = __float_as_uint(qs[(rl0 + 8) * QST + kk + lc + 4]);
#pragma unroll
                for (int nj = 0; nj < 2; nj++) {
                    int rn = wk * 16 + nj * 8 + lr;
                    uint32_t bf[2];
                    bf[0] = __float_as_uint(ks[rn * QST + kk + lc]);
                    bf[1] = __float_as_uint(ks[rn * QST + kk + lc + 4]);
                    mma_tf32(acc[ck * 2 + nj], a, bf, acc[ck * 2 + nj]);
                }
            }
        }

        // exp in place (single exp per score) + row partial sums
        float rs0 = 0.f, rs1 = 0.f;
#pragma unroll
        for (int tj = 0; tj < 16; tj++) {
            acc[tj][0] = __expf(acc[tj][0] * 0.125f);
            acc[tj][1] = __expf(acc[tj][1] * 0.125f);
            acc[tj][2] = __expf(acc[tj][2] * 0.125f);
            acc[tj][3] = __expf(acc[tj][3] * 0.125f);
            rs0 += acc[tj][0] + acc[tj][1];
            rs1 += acc[tj][2] + acc[tj][3];
        }
#pragma unroll
        for (int off = 1; off <= 2; off <<= 1) {
            rs0 += __shfl_xor_sync(0xffffffffu, rs0, off);
            rs1 += __shfl_xor_sync(0xffffffffu, rs1, off);
        }
        if (lc == 0) {
            ssum[wk][rl0] = rs0;
            ssum[wk][rl0 + 8] = rs1;
        }
        __syncthreads();
        float t0 = 0.f, t1 = 0.f;
#pragma unroll
        for (int j = 0; j < 8; j++) {
            t0 += ssum[j][rl0];
            t1 += ssum[j][rl0 + 8];
        }
        const float inv0 = 1.f / t0;
        const float inv1 = 1.f / t1;

        // write normalized attn + accumulate pav (thread-owned smem slots)
        float* arow0 = attn_out + (((size_t)(h * NB + b) * SS) + q0 + rl0) * SS;
        float* arow1 = arow0 + (size_t)8 * SS;
#pragma unroll
        for (int tj = 0; tj < 16; tj++) {
            int col = (tj >> 1) * 128 + wk * 16 + (tj & 1) * 8 + 2 * lc;
            float e0 = acc[tj][0] * inv0, e1 = acc[tj][1] * inv0;
            float e2 = acc[tj][2] * inv1, e3 = acc[tj][3] * inv1;
            *(float2*)(arow0 + col) = make_float2(e0, e1);
            *(float2*)(arow1 + col) = make_float2(e2, e3);
            float2* p0 = (float2*)(pav + rl0 * PST + col);
            float2 v0 = *p0; v0.x += e0; v0.y += e1; *p0 = v0;
            float2* p1 = (float2*)(pav + (rl0 + 8) * PST + col);
            float2 v1 = *p1; v1.x += e2; v1.y += e3; *p1 = v1;
        }
    }

    __syncthreads();
    // dump pav -> pavg (x 1/8)
    for (int i = tid; i < 32 * 256; i += 512) {
        int r = i >> 8, c4 = (i & 255) * 4;
        float4 v = *(float4*)(pav + r * PST + c4);
        v.x *= 0.125f; v.y *= 0.125f; v.z *= 0.125f; v.w *= 0.125f;
        *(float4*)(pavg + ((size_t)(b * SS + q0 + r)) * SS + c4) = v;
    }
}

// ---------------------------------------------------------------------------
extern "C" void kernel_launch(void* const* d_in, const int* in_sizes, int n_in,
                              void* d_out, int out_size) {
    const float* q  = (const float*)d_in[0];
    const float* k  = (const float*)d_in[1];
    const float* v  = (const float*)d_in[2];
    const float* Wq = (const float*)d_in[3];
    const float* Wk = (const float*)d_in[4];
    const float* Wv = (const float*)d_in[5];
    const float* Wo = (const float*)d_in[6];
    float* out  = (float*)d_out;
    float* attn = out + OUT_ELEMS;

    float *qh, *kh, *vs, *pavg, *head;
    cudaGetSymbolAddress((void**)&qh,   g_qh);
    cudaGetSymbolAddress((void**)&kh,   g_kh);
    cudaGetSymbolAddress((void**)&vs,   g_vs);
    cudaGetSymbolAddress((void**)&pavg, g_pavg);
    cudaGetSymbolAddress((void**)&head, g_head);

    cudaFuncSetAttribute(gemm_nt_mma2,
                         cudaFuncAttributeMaxDynamicSharedMemorySize, PROJ_SMEM);
    cudaFuncSetAttribute(attn_fused_kernel,
                         cudaFuncAttributeMaxDynamicSharedMemorySize, FUSED_SMEM);

    // Projections; qh/kh/vs emitted tf32-rounded (cvt_out=1)
    gemm_nt_mma2<<<dim3(DD / 64, MROWS / 128), 256, PROJ_SMEM>>>(q, Wq, qh, MROWS, DD, DD, 1);
    gemm_nt_mma2<<<dim3(DD / 64, MROWS / 128), 256, PROJ_SMEM>>>(k, Wk, kh, MROWS, DD, DD, 1);
    gemm_nt_mma2<<<dim3(DK / 64, MROWS / 128), 256, PROJ_SMEM>>>(v, Wv, vs, MROWS, DK, DD, 1);

    // Fused scores + softmax + attn + P_avg
    attn_fused_kernel<<<dim3(SS / 32, NB), 512, FUSED_SMEM>>>(qh, kh, attn, pavg);

    // head = P_avg @ vs (per batch)
    gemm_nn_mma<<<dim3(1, SS / 64, NB), 256>>>(
        pavg, vs, head, SS, DK, SS,
        (size_t)SS * SS, (size_t)SS * DK, (size_t)SS * DK);

    // out = head @ Wo^T (full fp32 output)
    gemm_nt_mma2<<<dim3(DD / 64, MROWS / 128), 256, PROJ_SMEM>>>(head, Wo, out, MROWS, DD, DK, 0);
}

// round 17
// speedup vs baseline: 1.4192x; 1.4192x over previous
// Round 17.
//
// Post-mortem R16: fused kernel was a big regression (445us total, fused
// 314us, tensor 8.9%, issue 20%). Model was wrong: shrinking the q-block to
// 32 rows to keep scores register-resident cut compute-per-K-byte 4x, so
// each tiny 16-MMA burst sat behind a full sync + DMA wait with 1 CTA/SM.
// Per theory-first matrix: revert to R14 (307.8us best) and re-evaluate.
//
// R14 budget: sums 65, write ~110-120, projections+nn+out ~130. attn_write
// is memory-bound by stream traffic: reads Q 128MB + K 256MB, writes
// 256MB attn + 32MB pavg = ~672MB total. The K read traffic scales with
// the number of q-blocks, so doubling the q-block 64 -> 128 rows (grid
// 1024 -> 512 CTAs, warp tile 32q x 64k like attn_sums) halves K reads
// (256 -> 128MB): total traffic 672 -> 544MB, and doubles compute per
// DMA'd byte. Registers: acc[2][8][4] + pav[2][8][4] = 128 floats persist;
// launch_bounds(256,1) (occupancy falls but the kernel is stream-bound
// with deep cp.async MLP). Everything else byte-identical to R14.
//
// Prediction: attn_write ~115 -> ~90-95us, total 307.8 -> ~280-290us,
// rel_err back to ~5.0e-4 (exact R14 numerics). If write lands >100us,
// traffic model is wrong and the next lever is the attn store path itself.

#include <cuda_runtime.h>
#include <cuda_bf16.h>
#include <math.h>
#include <stdint.h>

#define NB 8
#define SS 1024
#define DD 512
#define NH 8
#define DK 64
#define MROWS (NB * SS)
#define OUT_ELEMS (NB * SS * DD)

__device__ float g_qh[MROWS * DD];
__device__ float g_kh[MROWS * DD];
__device__ float g_vs[MROWS * DK];
__device__ float g_pavg[NB * SS * SS];
__device__ float g_head[MROWS * DK];
__device__ float g_rsuminv[NH * NB * SS];

__device__ __forceinline__ uint32_t f2tf32(float x) {
    uint32_t r;
    asm("cvt.rna.tf32.f32 %0, %1;" : "=r"(r) : "f"(x));
    return r;
}

__device__ __forceinline__ void mma_tf32(float* d, const uint32_t* a,
                                         const uint32_t* b, const float* c) {
    asm volatile(
        "mma.sync.aligned.m16n8k8.row.col.f32.tf32.tf32.f32 "
        "{%0,%1,%2,%3}, {%4,%5,%6,%7}, {%8,%9}, {%10,%11,%12,%13};"
        : "=f"(d[0]), "=f"(d[1]), "=f"(d[2]), "=f"(d[3])
        : "r"(a[0]), "r"(a[1]), "r"(a[2]), "r"(a[3]),
          "r"(b[0]), "r"(b[1]),
          "f"(c[0]), "f"(c[1]), "f"(c[2]), "f"(c[3]));
}

__device__ __forceinline__ void cp_async16(uint32_t dst, const void* src) {
    asm volatile("cp.async.cg.shared.global [%0], [%1], 16;" :: "r"(dst), "l"(src));
}
__device__ __forceinline__ void cp_commit() {
    asm volatile("cp.async.commit_group;");
}
__device__ __forceinline__ void cp_wait1() {
    asm volatile("cp.async.wait_group 1;");
}

__device__ __forceinline__ float maybe_tf32(float x, int cvt) {
    return cvt ? __uint_as_float(f2tf32(x)) : x;
}

// ---------------------------------------------------------------------------
// Pipelined MMA GEMM-NT: C[M,N] = A[M,K] * W[N,K]^T, tf32.
// ---------------------------------------------------------------------------
#define GST 36
#define PROJ_STAGE (192 * GST)
#define PROJ_SMEM (2 * PROJ_STAGE * 4)

__global__ __launch_bounds__(256, 2)
void gemm_nt_mma2(const float* __restrict__ A, const float* __restrict__ W,
                  float* __restrict__ C, int M, int N, int K, int cvt_out) {
    extern __shared__ float sm[];
    const int m0 = blockIdx.y * 128;
    const int n0 = blockIdx.x * 64;
    const int tid = threadIdx.x;
    const int wid = tid >> 5, lane = tid & 31;
    const int lr = lane >> 2, lc = lane & 3;
    const int wm = (wid >> 1) * 32;
    const int wn = (wid & 1) * 32;

    const uint32_t smem_base = (uint32_t)__cvta_generic_to_shared(sm);

    float acc[2][4][4] = {};
    const int kt = K / 32;

    {
        uint32_t As_u = smem_base;
        uint32_t Ws_u = smem_base + 128 * GST * 4;
#pragma unroll
        for (int t = 0; t < 4; t++) {
            int s = tid + t * 256;
            int r = s >> 3, c = (s & 7) * 4;
            cp_async16(As_u + (r * GST + c) * 4, A + (size_t)(m0 + r) * K + c);
        }
#pragma unroll
        for (int t = 0; t < 2; t++) {
            int s = tid + t * 256;
            int r = s >> 3, c = (s & 7) * 4;
            cp_async16(Ws_u + (r * GST + c) * 4, W + (size_t)(n0 + r) * K + c);
        }
    }
    cp_commit();

    for (int it = 0; it < kt; it++) {
        if (it + 1 < kt) {
            int k0 = (it + 1) * 32;
            uint32_t st = smem_base + ((it + 1) & 1) * PROJ_STAGE * 4;
            uint32_t As_u = st;
            uint32_t Ws_u = st + 128 * GST * 4;
#pragma unroll
            for (int t = 0; t < 4; t++) {
                int s = tid + t * 256;
                int r = s >> 3, c = (s & 7) * 4;
                cp_async16(As_u + (r * GST + c) * 4, A + (size_t)(m0 + r) * K + k0 + c);
            }
#pragma unroll
            for (int t = 0; t < 2; t++) {
                int s = tid + t * 256;
                int r = s >> 3, c = (s & 7) * 4;
                cp_async16(Ws_u + (r * GST + c) * 4, W + (size_t)(n0 + r) * K + k0 + c);
            }
        }
        cp_commit();
        cp_wait1();
        __syncthreads();

        const float* As = sm + (it & 1) * PROJ_STAGE;
        const float* Ws = As + 128 * GST;
#pragma unroll
        for (int kk = 0; kk < 32; kk += 8) {
            uint32_t a[2][4], b[4][2];
#pragma unroll
            for (int mi = 0; mi < 2; mi++) {
                int r0 = wm + mi * 16 + lr;
                a[mi][0] = f2tf32(As[r0 * GST + kk + lc]);
                a[mi][1] = f2tf32(As[(r0 + 8) * GST + kk + lc]);
                a[mi][2] = f2tf32(As[r0 * GST + kk + lc + 4]);
                a[mi][3] = f2tf32(As[(r0 + 8) * GST + kk + lc + 4]);
            }
#pragma unroll
            for (int nj = 0; nj < 4; nj++) {
                int rn = wn + nj * 8 + lr;
                b[nj][0] = f2tf32(Ws[rn * GST + kk + lc]);
                b[nj][1] = f2tf32(Ws[rn * GST + kk + lc + 4]);
            }
#pragma unroll
            for (int mi = 0; mi < 2; mi++)
#pragma unroll
                for (int nj = 0; nj < 4; nj++)
                    mma_tf32(acc[mi][nj], a[mi], b[nj], acc[mi][nj]);
        }
        __syncthreads();
    }

#pragma unroll
    for (int mi = 0; mi < 2; mi++) {
        int row = m0 + wm + mi * 16 + lr;
#pragma unroll
        for (int nj = 0; nj < 4; nj++) {
            int col = n0 + wn + nj * 8 + 2 * lc;
            *(float2*)(C + (size_t)row * N + col) =
                make_float2(maybe_tf32(acc[mi][nj][0], cvt_out),
                            maybe_tf32(acc[mi][nj][1], cvt_out));
            *(float2*)(C + (size_t)(row + 8) * N + col) =
                make_float2(maybe_tf32(acc[mi][nj][2], cvt_out),
                            maybe_tf32(acc[mi][nj][3], cvt_out));
        }
    }
}

// ---------------------------------------------------------------------------
// Pipelined batched MMA GEMM-NN: C_b[M,N] = A_b[M,K] * B_b[K,N], tf32.
// ---------------------------------------------------------------------------
#define NNST_A 36
#define NNST_B 72
#define NN_STAGE (64 * NNST_A + 32 * NNST_B)

__global__ __launch_bounds__(256, 2)
void gemm_nn_mma(const float* __restrict__ A, const float* __restrict__ B,
                 float* __restrict__ C, int M, int N, int K,
                 size_t strideA, size_t strideB, size_t strideC) {
    __shared__ float sm[2 * NN_STAGE];
    const float* Ab = A + (size_t)blockIdx.z * strideA;
    const float* Bb = B + (size_t)blockIdx.z * strideB;
    float* Cb = C + (size_t)blockIdx.z * strideC;
    const int m0 = blockIdx.y * 64;
    const int n0 = blockIdx.x * 64;
    const int tid = threadIdx.x;
    const int wid = tid >> 5, lane = tid & 31;
    const int lr = lane >> 2, lc = lane & 3;
    const int wm = (wid >> 1) * 16;
    const int wn = (wid & 1) * 32;

    const uint32_t smem_base = (uint32_t)__cvta_generic_to_shared(sm);
    float acc[4][4] = {};
    const int kt = K / 32;

    {
        uint32_t As_u = smem_base;
        uint32_t Bs_u = smem_base + 64 * NNST_A * 4;
#pragma unroll
        for (int t = 0; t < 2; t++) {
            int s = tid + t * 256;
            int r = s >> 3, c = (s & 7) * 4;
            cp_async16(As_u + (r * NNST_A + c) * 4, Ab + (size_t)(m0 + r) * K + c);
        }
#pragma unroll
        for (int t = 0; t < 2; t++) {
            int s = tid + t * 256;
            int r = s >> 4, c = (s & 15) * 4;
            cp_async16(Bs_u + (r * NNST_B + c) * 4, Bb + (size_t)r * N + n0 + c);
        }
    }
    cp_commit();

    for (int it = 0; it < kt; it++) {
        if (it + 1 < kt) {
            int k0 = (it + 1) * 32;
            uint32_t st = smem_base + ((it + 1) & 1) * NN_STAGE * 4;
            uint32_t As_u = st;
            uint32_t Bs_u = st + 64 * NNST_A * 4;
#pragma unroll
            for (int t = 0; t < 2; t++) {
                int s = tid + t * 256;
                int r = s >> 3, c = (s & 7) * 4;
                cp_async16(As_u + (r * NNST_A + c) * 4, Ab + (size_t)(m0 + r) * K + k0 + c);
            }
#pragma unroll
            for (int t = 0; t < 2; t++) {
                int s = tid + t * 256;
                int r = s >> 4, c = (s & 15) * 4;
                cp_async16(Bs_u + (r * NNST_B + c) * 4, Bb + (size_t)(k0 + r) * N + n0 + c);
            }
        }
        cp_commit();
        cp_wait1();
        __syncthreads();

        const float* As = sm + (it & 1) * NN_STAGE;
        const float* Bs = As + 64 * NNST_A;
#pragma unroll
        for (int kk = 0; kk < 32; kk += 8) {
            uint32_t a[4], b[4][2];
            int r0 = wm + lr;
            a[0] = f2tf32(As[r0 * NNST_A + kk + lc]);
            a[1] = f2tf32(As[(r0 + 8) * NNST_A + kk + lc]);
            a[2] = f2tf32(As[r0 * NNST_A + kk + lc + 4]);
            a[3] = f2tf32(As[(r0 + 8) * NNST_A + kk + lc + 4]);
#pragma unroll
            for (int nj = 0; nj < 4; nj++) {
                int rn = wn + nj * 8 + lr;
                b[nj][0] = __float_as_uint(Bs[(kk + lc) * NNST_B + rn]);
                b[nj][1] = __float_as_uint(Bs[(kk + lc + 4) * NNST_B + rn]);
            }
#pragma unroll
            for (int nj = 0; nj < 4; nj++)
                mma_tf32(acc[nj], a, b[nj], acc[nj]);
        }
        __syncthreads();
    }

    {
        int row = m0 + wm + lr;
#pragma unroll
        for (int nj = 0; nj < 4; nj++) {
            int col = n0 + wn + nj * 8 + 2 * lc;
            *(float2*)(Cb + (size_t)row * N + col) =
                make_float2(acc[nj][0], acc[nj][1]);
            *(float2*)(Cb + (size_t)(row + 8) * N + col) =
                make_float2(acc[nj][2], acc[nj][3]);
        }
    }
}

// ---------------------------------------------------------------------------
// Pass 1: row sums of exp(score). Identical to R14 (65.4us measured).
// ---------------------------------------------------------------------------
#define QST 68
#define KCH_F (128 * QST)
#define SUMS_SMEM ((128 * QST + 2 * KCH_F) * 4)

__global__ __launch_bounds__(256, 2)
void attn_sums_kernel(const float* __restrict__ qh,
                      const float* __restrict__ kh,
                      float* __restrict__ rsuminv) {
    extern __shared__ float smf[];
    const float* qs = smf;
    const float* ks = smf + 128 * QST;
    __shared__ float ssum[2][128];

    const int q0 = blockIdx.x * 128;
    const int h = blockIdx.y;
    const int b = blockIdx.z;
    const int tid = threadIdx.x;
    const int wid = tid >> 5, lane = tid & 31;
    const int lr = lane >> 2, lc = lane & 3;
    const int wq = wid >> 1, wk = wid & 1;

    const uint32_t qs_u = (uint32_t)__cvta_generic_to_shared(smf);
    const uint32_t ks_u = qs_u + 128 * QST * 4;

    const float* qbase = qh + ((size_t)(b * SS + q0)) * DD + h * DK;
    const float* kbase = kh + ((size_t)b * SS) * DD + h * DK;

    {
#pragma unroll
        for (int t = 0; t < 8; t++) {
            int s = tid + t * 256;
            int r = s >> 4, c4 = (s & 15) * 4;
            cp_async16(qs_u + (r * QST + c4) * 4, qbase + (size_t)r * DD + c4);
        }
#pragma unroll
        for (int t = 0; t < 8; t++) {
            int s = tid + t * 256;
            int r = s >> 4, c4 = (s & 15) * 4;
            cp_async16(ks_u + (r * QST + c4) * 4, kbase + (size_t)r * DD + c4);
        }
    }
    cp_commit();

    float rs[2][2] = {};

    for (int ck = 0; ck < SS / 128; ck++) {
        if (ck + 1 < SS / 128) {
            uint32_t dst = ks_u + ((ck + 1) & 1) * KCH_F * 4;
            const float* src = kbase + (size_t)(ck + 1) * 128 * DD;
#pragma unroll
            for (int t = 0; t < 8; t++) {
                int s = tid + t * 256;
                int r = s >> 4, c4 = (s & 15) * 4;
                cp_async16(dst + (r * QST + c4) * 4, src + (size_t)r * DD + c4);
            }
        }
        cp_commit();
        cp_wait1();
        __syncthreads();

        const float* kst = ks + (ck & 1) * KCH_F;

        float acc[2][8][4] = {};
#pragma unroll
        for (int kk = 0; kk < DK; kk += 8) {
            uint32_t a[2][4];
#pragma unroll
            for (int mi = 0; mi < 2; mi++) {
                int r0 = wq * 32 + mi * 16 + lr;
                a[mi][0] = __float_as_uint(qs[r0 * QST + kk + lc]);
                a[mi][1] = __float_as_uint(qs[(r0 + 8) * QST + kk + lc]);
                a[mi][2] = __float_as_uint(qs[r0 * QST + kk + lc + 4]);
                a[mi][3] = __float_as_uint(qs[(r0 + 8) * QST + kk + lc + 4]);
            }
#pragma unroll
            for (int nj = 0; nj < 8; nj++) {
                int rn = wk * 64 + nj * 8 + lr;
                uint32_t bf[2];
                bf[0] = __float_as_uint(kst[rn * QST + kk + lc]);
                bf[1] = __float_as_uint(kst[rn * QST + kk + lc + 4]);
                mma_tf32(acc[0][nj], a[0], bf, acc[0][nj]);
                mma_tf32(acc[1][nj], a[1], bf, acc[1][nj]);
            }
        }
#pragma unroll
        for (int mi = 0; mi < 2; mi++)
#pragma unroll
            for (int nj = 0; nj < 8; nj++) {
                rs[mi][0] += __expf(acc[mi][nj][0] * 0.125f) + __expf(acc[mi][nj][1] * 0.125f);
                rs[mi][1] += __expf(acc[mi][nj][2] * 0.125f) + __expf(acc[mi][nj][3] * 0.125f);
            }
        __syncthreads();
    }
#pragma unroll
    for (int off = 1; off <= 2; off <<= 1) {
#pragma unroll
        for (int mi = 0; mi < 2; mi++) {
            rs[mi][0] += __shfl_xor_sync(0xffffffffu, rs[mi][0], off);
            rs[mi][1] += __shfl_xor_sync(0xffffffffu, rs[mi][1], off);
        }
    }
    if (lc == 0) {
#pragma unroll
        for (int mi = 0; mi < 2; mi++) {
            ssum[wk][wq * 32 + mi * 16 + lr] = rs[mi][0];
            ssum[wk][wq * 32 + mi * 16 + lr + 8] = rs[mi][1];
        }
    }
    __syncthreads();
    if (tid < 128)
        rsuminv[(size_t)(h * NB + b) * SS + q0 + tid] =
            1.f / (ssum[0][tid] + ssum[1][tid]);
}

// ---------------------------------------------------------------------------
// Pass 2 (new tiling): 128 q rows x one 128-key chunk x b; grid 512 CTAs.
// 8 warps, warp tile 32q x 64k (wq 4 x wk 2). Heads double-buffered via
// cp.async. Persistent pav[2][8][4] per thread across heads.
// Stage = (128+128)x68 floats = 69,632B; 2 stages = 139,264B dynamic.
// ---------------------------------------------------------------------------
#define WR_STAGE (256 * QST)
#define WRITE_SMEM (2 * WR_STAGE * 4)

__global__ __launch_bounds__(256, 1)
void attn_write_kernel(const float* __restrict__ qh,
                       const float* __restrict__ kh,
                       const float* __restrict__ rsuminv,
                       float* __restrict__ attn_out,
                       float* __restrict__ pavg) {
    extern __shared__ float smf[];

    const int q0 = blockIdx.x * 128;
    const int ck = blockIdx.y;
    const int b = blockIdx.z;
    const int kb = ck * 128;
    const int tid = threadIdx.x;
    const int wid = tid >> 5, lane = tid & 31;
    const int lr = lane >> 2, lc = lane & 3;
    const int wq = wid >> 1, wk = wid & 1;

    const uint32_t smem_base = (uint32_t)__cvta_generic_to_shared(smf);

    const float* qb0 = qh + ((size_t)(b * SS + q0)) * DD;
    const float* kb0 = kh + ((size_t)(b * SS + kb)) * DD;

    // prologue: head 0 Q (128 rows) + K (128 rows), 8 float4/thread each
    {
        uint32_t qd = smem_base;
        uint32_t kd = smem_base + 128 * QST * 4;
#pragma unroll
        for (int t = 0; t < 8; t++) {
            int s = tid + t * 256;
            int r = s >> 4, c4 = (s & 15) * 4;
            cp_async16(qd + (r * QST + c4) * 4, qb0 + (size_t)r * DD + c4);
            cp_async16(kd + (r * QST + c4) * 4, kb0 + (size_t)r * DD + c4);
        }
    }
    cp_commit();

    float pav[2][8][4] = {};

    for (int h = 0; h < NH; h++) {
        if (h + 1 < NH) {
            uint32_t st = smem_base + ((h + 1) & 1) * WR_STAGE * 4;
            uint32_t qd = st;
            uint32_t kd = st + 128 * QST * 4;
            const float* qsrc = qb0 + (h + 1) * DK;
            const float* ksrc = kb0 + (h + 1) * DK;
#pragma unroll
            for (int t = 0; t < 8; t++) {
                int s = tid + t * 256;
                int r = s >> 4, c4 = (s & 15) * 4;
                cp_async16(qd + (r * QST + c4) * 4, qsrc + (size_t)r * DD + c4);
                cp_async16(kd + (r * QST + c4) * 4, ksrc + (size_t)r * DD + c4);
            }
        }
        cp_commit();
        cp_wait1();
        __syncthreads();

        const float* qs = smf + (h & 1) * WR_STAGE;
        const float* ks = qs + 128 * QST;

        float acc[2][8][4] = {};
#pragma unroll
        for (int kk = 0; kk < DK; kk += 8) {
            uint32_t a[2][4];
#pragma unroll
            for (int mi = 0; mi < 2; mi++) {
                int r0 = wq * 32 + mi * 16 + lr;
                a[mi][0] = __float_as_uint(qs[r0 * QST + kk + lc]);
                a[mi][1] = __float_as_uint(qs[(r0 + 8) * QST + kk + lc]);
                a[mi][2] = __float_as_uint(qs[r0 * QST + kk + lc + 4]);
                a[mi][3] = __float_as_uint(qs[(r0 + 8) * QST + kk + lc + 4]);
            }
#pragma unroll
            for (int nj = 0; nj < 8; nj++) {
                int rn = wk * 64 + nj * 8 + lr;
                uint32_t bf[2];
                bf[0] = __float_as_uint(ks[rn * QST + kk + lc]);
                bf[1] = __float_as_uint(ks[rn * QST + kk + lc + 4]);
                mma_tf32(acc[0][nj], a[0], bf, acc[0][nj]);
                mma_tf32(acc[1][nj], a[1], bf, acc[1][nj]);
            }
        }

        const float* rinv = rsuminv + (size_t)(h * NB + b) * SS + q0;
#pragma unroll
        for (int mi = 0; mi < 2; mi++) {
            int rl = wq * 32 + mi * 16 + lr;
            const float inv0 = rinv[rl];
            const float inv1 = rinv[rl + 8];
            float* arow0 = attn_out + (((size_t)(h * NB + b) * SS) + q0 + rl) * SS + kb;
            float* arow1 = arow0 + (size_t)8 * SS;
#pragma unroll
            for (int nj = 0; nj < 8; nj++) {
                int col = wk * 64 + nj * 8 + 2 * lc;
                float e0 = __expf(acc[mi][nj][0] * 0.125f) * inv0;
                float e1 = __expf(acc[mi][nj][1] * 0.125f) * inv0;
                float e2 = __expf(acc[mi][nj][2] * 0.125f) * inv1;
                float e3 = __expf(acc[mi][nj][3] * 0.125f) * inv1;
                *(float2*)(arow0 + col) = make_float2(e0, e1);
                *(float2*)(arow1 + col) = make_float2(e2, e3);
                pav[mi][nj][0] += e0; pav[mi][nj][1] += e1;
                pav[mi][nj][2] += e2; pav[mi][nj][3] += e3;
            }
        }
        __syncthreads();
    }

#pragma unroll
    for (int mi = 0; mi < 2; mi++) {
        int rl = wq * 32 + mi * 16 + lr;
        float* prow0 = pavg + ((size_t)b * SS + q0 + rl) * SS + kb;
        float* prow1 = prow0 + (size_t)8 * SS;
#pragma unroll
        for (int nj = 0; nj < 8; nj++) {
            int col = wk * 64 + nj * 8 + 2 * lc;
            *(float2*)(prow0 + col) =
                make_float2(pav[mi][nj][0] * 0.125f, pav[mi][nj][1] * 0.125f);
            *(float2*)(prow1 + col) =
                make_float2(pav[mi][nj][2] * 0.125f, pav[mi][nj][3] * 0.125f);
        }
    }
}

// ---------------------------------------------------------------------------
extern "C" void kernel_launch(void* const* d_in, const int* in_sizes, int n_in,
                              void* d_out, int out_size) {
    const float* q  = (const float*)d_in[0];
    const float* k  = (const float*)d_in[1];
    const float* v  = (const float*)d_in[2];
    const float* Wq = (const float*)d_in[3];
    const float* Wk = (const float*)d_in[4];
    const float* Wv = (const float*)d_in[5];
    const float* Wo = (const float*)d_in[6];
    float* out  = (float*)d_out;
    float* attn = out + OUT_ELEMS;

    float *qh, *kh, *vs, *pavg, *head, *rsuminv;
    cudaGetSymbolAddress((void**)&qh,      g_qh);
    cudaGetSymbolAddress((void**)&kh,      g_kh);
    cudaGetSymbolAddress((void**)&vs,      g_vs);
    cudaGetSymbolAddress((void**)&pavg,    g_pavg);
    cudaGetSymbolAddress((void**)&head,    g_head);
    cudaGetSymbolAddress((void**)&rsuminv, g_rsuminv);

    cudaFuncSetAttribute(gemm_nt_mma2,
                         cudaFuncAttributeMaxDynamicSharedMemorySize, PROJ_SMEM);
    cudaFuncSetAttribute(attn_sums_kernel,
                         cudaFuncAttributeMaxDynamicSharedMemorySize, SUMS_SMEM);
    cudaFuncSetAttribute(attn_write_kernel,
                         cudaFuncAttributeMaxDynamicSharedMemorySize, WRITE_SMEM);

    // Projections; qh/kh/vs emitted tf32-rounded (cvt_out=1)
    gemm_nt_mma2<<<dim3(DD / 64, MROWS / 128), 256, PROJ_SMEM>>>(q, Wq, qh, MROWS, DD, DD, 1);
    gemm_nt_mma2<<<dim3(DD / 64, MROWS / 128), 256, PROJ_SMEM>>>(k, Wk, kh, MROWS, DD, DD, 1);
    gemm_nt_mma2<<<dim3(DK / 64, MROWS / 128), 256, PROJ_SMEM>>>(v, Wv, vs, MROWS, DK, DD, 1);

    attn_sums_kernel<<<dim3(SS / 128, NH, NB), 256, SUMS_SMEM>>>(qh, kh, rsuminv);

    attn_write_kernel<<<dim3(SS / 128, SS / 128, NB), 256, WRITE_SMEM>>>(
        qh, kh, rsuminv, attn, pavg);

    gemm_nn_mma<<<dim3(1, SS / 64, NB), 256>>>(
        pavg, vs, head, SS, DK, SS,
        (size_t)SS * SS, (size_t)SS * DK, (size_t)SS * DK);

    // Final out projection: full fp32 output (cvt_out=0)
    gemm_nt_mma2<<<dim3(DD / 64, MROWS / 128), 256, PROJ_SMEM>>>(head, Wo, out, MROWS, DD, DK, 0);
}